// round 2
// baseline (speedup 1.0000x reference)
#include <cuda_runtime.h>
#include <cstdint>

#define NN 100000
#define EE 3200000
#define DD 64

// Scratch (static __device__ arrays; no allocation allowed)
__device__ int   g_deg[NN];
__device__ float g_dinv[NN];
__device__ float g_norm[EE];
__device__ int   g_row[EE];
__device__ int   g_col[EE];
__device__ __align__(16) float g_xa[NN * DD];
__device__ __align__(16) float g_xb[NN * DD];

__global__ void zero_deg_kernel() {
    int i = blockIdx.x * blockDim.x + threadIdx.x;
    if (i < NN) g_deg[i] = 0;
}

__global__ void count_deg_kernel(const int* __restrict__ col32) {
    int e = blockIdx.x * blockDim.x + threadIdx.x;
    if (e < EE) {
        int c = col32[e];
        if (c >= 0 && c < NN) atomicAdd(&g_deg[c], 1);
    }
}

__global__ void dinv_kernel() {
    int i = blockIdx.x * blockDim.x + threadIdx.x;
    if (i < NN) {
        int d = g_deg[i];
        g_dinv[i] = (d > 0) ? rsqrtf((float)d) : 0.0f;
    }
}

__global__ void prep_edges_kernel(const int* __restrict__ row32,
                                  const int* __restrict__ col32) {
    int e = blockIdx.x * blockDim.x + threadIdx.x;
    if (e < EE) {
        int r = row32[e];
        int c = col32[e];
        // defensive clamp: out-of-range edges become self-edges on node 0 with 0 weight
        bool ok = (r >= 0 && r < NN && c >= 0 && c < NN);
        g_row[e] = ok ? r : 0;
        g_col[e] = ok ? c : 0;
        g_norm[e] = ok ? g_dinv[r] * g_dinv[c] : 0.0f;
    }
}

// acc (d_out) = emb ; x_a = emb
__global__ void init_kernel(const float* __restrict__ emb, float* __restrict__ out) {
    int i = blockIdx.x * blockDim.x + threadIdx.x;
    if (i < NN * DD) {
        float v = emb[i];
        g_xa[i] = v;
        out[i] = v;
    }
}

// zero one of the ping-pong buffers. which==0 -> zero g_xb, which==1 -> zero g_xa
__global__ void zero_x_kernel(int which) {
    int i = blockIdx.x * blockDim.x + threadIdx.x;
    if (i < NN * DD) {
        if (which == 0) g_xb[i] = 0.0f;
        else            g_xa[i] = 0.0f;
    }
}

// Edge-parallel scatter: one thread per (edge, 4-float chunk).
// dir==0: read g_xa, scatter into g_xb ; dir==1: read g_xb, scatter into g_xa
template <int DIR>
__global__ __launch_bounds__(256) void scatter_kernel() {
    long long idx = (long long)blockIdx.x * blockDim.x + threadIdx.x;
    if (idx >= (long long)EE * 16) return;
    int e = (int)(idx >> 4);
    int c = (int)(idx & 15);

    int r  = __ldg(&g_row[e]);
    int co = __ldg(&g_col[e]);
    float nm = __ldg(&g_norm[e]);

    const float* xin  = DIR == 0 ? g_xa : g_xb;
    float*       xout = DIR == 0 ? g_xb : g_xa;

    const float4* src = reinterpret_cast<const float4*>(xin + (long long)r * DD) + c;
    float4 v = __ldg(src);
    v.x *= nm; v.y *= nm; v.z *= nm; v.w *= nm;

    float4* dst = reinterpret_cast<float4*>(xout + (long long)co * DD) + c;
    asm volatile("red.global.add.v4.f32 [%0], {%1,%2,%3,%4};"
                 :: "l"(dst), "f"(v.x), "f"(v.y), "f"(v.z), "f"(v.w)
                 : "memory");
}

// out = (out + x) * scale, where x = (which==0 ? g_xb : g_xa)
__global__ void accum_kernel(float* __restrict__ out, int which, float scale) {
    int i = blockIdx.x * blockDim.x + threadIdx.x;
    if (i < NN * DD) {
        float xv = (which == 0) ? g_xb[i] : g_xa[i];
        out[i] = (out[i] + xv) * scale;
    }
}

extern "C" void kernel_launch(void* const* d_in, const int* in_sizes, int n_in,
                              void* d_out, int out_size) {
    const float* emb = (const float*)d_in[0];
    const int* edge = (const int*)d_in[1];  // [2, EE] int32 (JAX x64-disabled downcast)
    const int* row32 = edge;
    const int* col32 = edge + EE;
    float* out = (float*)d_out;

    const int T = 256;
    int gN  = (NN + T - 1) / T;
    int gE  = (EE + T - 1) / T;
    int gND = (NN * DD + T - 1) / T;
    int gS  = (int)(((long long)EE * 16 + T - 1) / T);

    // --- preprocessing (per call; graph-capturable kernel launches only) ---
    zero_deg_kernel<<<gN, T>>>();
    count_deg_kernel<<<gE, T>>>(col32);
    dinv_kernel<<<gN, T>>>();
    prep_edges_kernel<<<gE, T>>>(row32, col32);
    init_kernel<<<gND, T>>>(emb, out);

    // --- layer 0: xa -> xb ---
    zero_x_kernel<<<gND, T>>>(0);
    scatter_kernel<0><<<gS, T>>>();
    accum_kernel<<<gND, T>>>(out, 0, 1.0f);

    // --- layer 1: xb -> xa ---
    zero_x_kernel<<<gND, T>>>(1);
    scatter_kernel<1><<<gS, T>>>();
    accum_kernel<<<gND, T>>>(out, 1, 1.0f);

    // --- layer 2: xa -> xb (fold /4 into last accumulate) ---
    zero_x_kernel<<<gND, T>>>(0);
    scatter_kernel<0><<<gS, T>>>();
    accum_kernel<<<gND, T>>>(out, 0, 0.25f);
}